// round 1
// baseline (speedup 1.0000x reference)
#include <cuda_runtime.h>
#include <cuda_bf16.h>
#include <math_constants.h>

// Problem constants (fixed by the dataset)
#define NMAX 50000
#define EMAX 300000
#define GNUM 64
#define DH   256
#define DIN  512

// ---------------- scratch (device globals: no allocs allowed) ----------------
__device__ float g_x[(size_t)NMAX * 512];        // embedded node features (layer-1 input)
__device__ float g_qkvs[(size_t)NMAX * 1024];    // [q|k|v|skip] per node
__device__ float g_h0[(size_t)NMAX * 256];       // layer-1 output
__device__ float g_h1[(size_t)NMAX * 256];       // layer-2 output
__device__ int   g_deg[NMAX];
__device__ int   g_rowptr[NMAX + 1];
__device__ int   g_cursor[NMAX];
__device__ int   g_eids[EMAX];
__device__ float g_gap[GNUM * 256];
__device__ unsigned g_gmp[GNUM * 256];           // float bits (values >= 0 post-relu)
__device__ int   g_cnt[GNUM];

// ---------------- 1. embedding gather: x[n, f*64+j] = emb[x_idx[n,f], j] ----
__global__ void embed_kernel(const int* __restrict__ xidx,
                             const float* __restrict__ emb, int N)
{
    long i = (long)blockIdx.x * blockDim.x + threadIdx.x;
    long total = (long)N * 512;
    if (i >= total) return;
    int n = (int)(i >> 9);
    int k = (int)(i & 511);
    int f = k >> 6, j = k & 63;
    g_x[i] = emb[(size_t)xidx[n * 8 + f] * 64 + j];
}

// ---------------- 2. zero counters -----------------------------------------
__global__ void init_kernel(int N)
{
    int i = blockIdx.x * blockDim.x + threadIdx.x;
    int stride = gridDim.x * blockDim.x;
    for (int j = i; j < N; j += stride) g_deg[j] = 0;
    for (int j = i; j < GNUM * 256; j += stride) { g_gap[j] = 0.f; g_gmp[j] = 0u; }
    for (int j = i; j < GNUM; j += stride) g_cnt[j] = 0;
}

// ---------------- 3. CSR build ----------------------------------------------
__global__ void count_kernel(const int* __restrict__ dst, int E)
{
    int e = blockIdx.x * blockDim.x + threadIdx.x;
    if (e < E) atomicAdd(&g_deg[dst[e]], 1);
}

__global__ void scan_kernel(int N)
{
    __shared__ int sm[1024];
    __shared__ int carry;
    int tid = threadIdx.x;
    if (tid == 0) { carry = 0; g_rowptr[0] = 0; }
    __syncthreads();
    for (int base = 0; base < N; base += 1024) {
        int i = base + tid;
        int v = (i < N) ? g_deg[i] : 0;
        sm[tid] = v;
        __syncthreads();
        #pragma unroll
        for (int off = 1; off < 1024; off <<= 1) {
            int t = (tid >= off) ? sm[tid - off] : 0;
            __syncthreads();
            sm[tid] += t;
            __syncthreads();
        }
        int incl = sm[tid];
        if (i < N) {
            g_rowptr[i + 1] = carry + incl;
            g_cursor[i]     = carry + incl - v;
        }
        __syncthreads();
        if (tid == 1023) carry += sm[1023];
        __syncthreads();
    }
}

__global__ void fill_kernel(const int* __restrict__ dst, int E)
{
    int e = blockIdx.x * blockDim.x + threadIdx.x;
    if (e < E) {
        int pos = atomicAdd(&g_cursor[dst[e]], 1);
        g_eids[pos] = e;
    }
}

// ---------------- 4. fused 4-matrix GEMM: C[N,1024] = A @ [Wq|Wk|Wv|Ws]^T + b
// A row-major [M,K], W row-major [256,K]. 128x128 tile, 8x8 per thread.
__global__ void __launch_bounds__(256) gemm_kernel(
    int layer, int M, int K,
    const float* __restrict__ W0, const float* __restrict__ W1,
    const float* __restrict__ W2, const float* __restrict__ W3,
    const float* __restrict__ Bi0, const float* __restrict__ Bi1,
    const float* __restrict__ Bi2, const float* __restrict__ Bi3)
{
    const float* A = (layer == 0) ? g_x : g_h0;
    float* C = g_qkvs;
    const int ldc = 1024;

    int bn = blockIdx.x;   // 0..7 : which 128-wide column tile
    int bm = blockIdx.y;
    const float* W  = (bn < 2) ? W0  : (bn < 4) ? W1  : (bn < 6) ? W2  : W3;
    const float* Bi = (bn < 2) ? Bi0 : (bn < 4) ? Bi1 : (bn < 6) ? Bi2 : Bi3;
    int nloc = (bn & 1) * 128;      // row offset inside the 256-row weight

    __shared__ float As[8][128];
    __shared__ float Bs[8][128];

    int tid  = threadIdx.x;
    int arow = tid >> 1;            // 0..127
    int ac4  = (tid & 1) * 4;       // 0 or 4
    int tm0  = (tid >> 4) * 8;      // 0..120
    int tn0  = (tid & 15) * 8;

    bool aval = (bm * 128 + arow) < M;
    const float* Arow = A + (size_t)(bm * 128 + arow) * K;
    const float* Wrow = W + (size_t)(nloc + arow) * K;

    float acc[8][8];
    #pragma unroll
    for (int i = 0; i < 8; i++)
        #pragma unroll
        for (int j = 0; j < 8; j++) acc[i][j] = 0.f;

    for (int k0 = 0; k0 < K; k0 += 8) {
        float4 av = aval ? *(const float4*)(Arow + k0 + ac4) : make_float4(0, 0, 0, 0);
        float4 bv = *(const float4*)(Wrow + k0 + ac4);
        As[ac4 + 0][arow] = av.x; As[ac4 + 1][arow] = av.y;
        As[ac4 + 2][arow] = av.z; As[ac4 + 3][arow] = av.w;
        Bs[ac4 + 0][arow] = bv.x; Bs[ac4 + 1][arow] = bv.y;
        Bs[ac4 + 2][arow] = bv.z; Bs[ac4 + 3][arow] = bv.w;
        __syncthreads();
        #pragma unroll
        for (int kk = 0; kk < 8; kk++) {
            float a[8], b[8];
            *(float4*)&a[0] = *(const float4*)&As[kk][tm0];
            *(float4*)&a[4] = *(const float4*)&As[kk][tm0 + 4];
            *(float4*)&b[0] = *(const float4*)&Bs[kk][tn0];
            *(float4*)&b[4] = *(const float4*)&Bs[kk][tn0 + 4];
            #pragma unroll
            for (int i = 0; i < 8; i++)
                #pragma unroll
                for (int j = 0; j < 8; j++) acc[i][j] += a[i] * b[j];
        }
        __syncthreads();
    }

    #pragma unroll
    for (int i = 0; i < 8; i++) {
        int m = bm * 128 + tm0 + i;
        if (m >= M) continue;
        float out[8];
        #pragma unroll
        for (int j = 0; j < 8; j++) out[j] = acc[i][j] + Bi[nloc + tn0 + j];
        float* cp = C + (size_t)m * ldc + bn * 128 + tn0;
        *(float4*)cp       = *(const float4*)&out[0];
        *(float4*)(cp + 4) = *(const float4*)&out[4];
    }
}

// ---------------- 5. fused edge attention: 1 warp per dst node --------------
// Online softmax over incoming edges; e = edge_attr @ we^T + be recomputed in regs.
__global__ void __launch_bounds__(256) attn_kernel(
    int layer,
    const int* __restrict__ esrc, const float* __restrict__ eattr,
    const float* __restrict__ we, const float* __restrict__ be, int N)
{
    int warp = (int)((blockIdx.x * 256 + threadIdx.x) >> 5);
    int lane = threadIdx.x & 31;
    if (warp >= N) return;
    float* hout = layer ? g_h1 : g_h0;

    int d0 = lane * 8;
    float wE[8][6], bE[8];
    #pragma unroll
    for (int i = 0; i < 8; i++) {
        bE[i] = be[d0 + i];
        #pragma unroll
        for (int j = 0; j < 6; j++) wE[i][j] = we[(d0 + i) * 6 + j];
    }

    const float* base = g_qkvs + (size_t)warp * 1024;
    float q[8];
    {
        float4 t0 = *(const float4*)(base + d0);
        float4 t1 = *(const float4*)(base + d0 + 4);
        q[0] = t0.x; q[1] = t0.y; q[2] = t0.z; q[3] = t0.w;
        q[4] = t1.x; q[5] = t1.y; q[6] = t1.z; q[7] = t1.w;
    }

    float m = -CUDART_INF_F, s = 0.f;
    float acc[8] = {0, 0, 0, 0, 0, 0, 0, 0};
    int beg = g_rowptr[warp], end = g_rowptr[warp + 1];

    for (int p = beg; p < end; p++) {
        int eid = g_eids[p];
        int src = esrc[eid];
        float eav = (lane < 6) ? eattr[(size_t)eid * 6 + lane] : 0.f;

        const float* kb = g_qkvs + (size_t)src * 1024 + 256;
        float4 k0 = *(const float4*)(kb + d0);
        float4 k1 = *(const float4*)(kb + d0 + 4);
        float4 v0 = *(const float4*)(kb + 256 + d0);
        float4 v1 = *(const float4*)(kb + 256 + d0 + 4);

        float e6[6];
        #pragma unroll
        for (int j = 0; j < 6; j++) e6[j] = __shfl_sync(0xffffffffu, eav, j);

        float e8[8];
        #pragma unroll
        for (int i = 0; i < 8; i++) {
            float t = bE[i];
            #pragma unroll
            for (int j = 0; j < 6; j++) t += wE[i][j] * e6[j];
            e8[i] = t;
        }
        float kk[8] = {k0.x + e8[0], k0.y + e8[1], k0.z + e8[2], k0.w + e8[3],
                       k1.x + e8[4], k1.y + e8[5], k1.z + e8[6], k1.w + e8[7]};
        float vv[8] = {v0.x + e8[0], v0.y + e8[1], v0.z + e8[2], v0.w + e8[3],
                       v1.x + e8[4], v1.y + e8[5], v1.z + e8[6], v1.w + e8[7]};
        float t = 0.f;
        #pragma unroll
        for (int i = 0; i < 8; i++) t += q[i] * kk[i];
        #pragma unroll
        for (int off = 16; off; off >>= 1) t += __shfl_xor_sync(0xffffffffu, t, off);
        float logit = t * 0.0625f;               // / sqrt(256)

        float nm = fmaxf(m, logit);
        float sc = __expf(m - nm);               // m=-inf on first edge -> 0
        float pw = __expf(logit - nm);
        s = s * sc + pw;
        #pragma unroll
        for (int i = 0; i < 8; i++) acc[i] = acc[i] * sc + pw * vv[i];
        m = nm;
    }

    float inv = (s > 0.f) ? (1.f / s) : 0.f;
    const float* sk = base + 768;
    float4 s0 = *(const float4*)(sk + d0);
    float4 s1 = *(const float4*)(sk + d0 + 4);
    float o[8] = {fmaxf(acc[0] * inv + s0.x, 0.f), fmaxf(acc[1] * inv + s0.y, 0.f),
                  fmaxf(acc[2] * inv + s0.z, 0.f), fmaxf(acc[3] * inv + s0.w, 0.f),
                  fmaxf(acc[4] * inv + s1.x, 0.f), fmaxf(acc[5] * inv + s1.y, 0.f),
                  fmaxf(acc[6] * inv + s1.z, 0.f), fmaxf(acc[7] * inv + s1.w, 0.f)};
    float* hp = hout + (size_t)warp * 256 + d0;
    *(float4*)hp       = *(const float4*)&o[0];
    *(float4*)(hp + 4) = *(const float4*)&o[4];
}

// ---------------- 6. pooling: sorted batch -> run-accumulated atomics -------
#define POOL_CHUNK 512
__global__ void __launch_bounds__(256) pool_kernel(const int* __restrict__ batch, int N)
{
    int d  = threadIdx.x;                 // 0..255 (one dim per thread)
    int n0 = blockIdx.x * POOL_CHUNK;
    if (n0 >= N) return;
    int n1 = min(n0 + POOL_CHUNK, N);

    int cur = batch[n0];
    float sum = 0.f, mx = 0.f;
    int run = 0;
    for (int n = n0; n < n1; n++) {
        int g = batch[n];
        if (g != cur) {
            atomicAdd(&g_gap[cur * 256 + d], sum);
            atomicMax(&g_gmp[cur * 256 + d], __float_as_uint(mx));
            if (d == 0) atomicAdd(&g_cnt[cur], run);
            sum = 0.f; mx = 0.f; run = 0; cur = g;
        }
        float v = g_h1[(size_t)n * 256 + d];
        sum += v; mx = fmaxf(mx, v); run++;
    }
    atomicAdd(&g_gap[cur * 256 + d], sum);
    atomicMax(&g_gmp[cur * 256 + d], __float_as_uint(mx));
    if (d == 0) atomicAdd(&g_cnt[cur], run);
}

// ---------------- 7. head MLP: one CTA per graph -----------------------------
__global__ void __launch_bounds__(256) mlp_kernel(
    const float* __restrict__ w1, const float* __restrict__ b1,
    const float* __restrict__ w2, const float* __restrict__ b2,
    const float* __restrict__ w3, const float* __restrict__ b3,
    float* __restrict__ out)
{
    int g = blockIdx.x;
    int t = threadIdx.x;
    __shared__ float r[512];
    __shared__ float o1[256];
    __shared__ float o2[128];
    __shared__ float red[256];

    float c = fmaxf((float)g_cnt[g], 1.f);
    r[t]       = g_gap[g * 256 + t] / c;
    r[256 + t] = __uint_as_float(g_gmp[g * 256 + t]);
    __syncthreads();

    {
        float a = b1[t];
        const float* wr = w1 + (size_t)t * 512;
        #pragma unroll 8
        for (int i = 0; i < 512; i++) a += wr[i] * r[i];
        o1[t] = fmaxf(a, 0.f);
    }
    __syncthreads();
    if (t < 128) {
        float a = b2[t];
        const float* wr = w2 + (size_t)t * 256;
        #pragma unroll 8
        for (int i = 0; i < 256; i++) a += wr[i] * o1[i];
        o2[t] = fmaxf(a, 0.f);
    }
    __syncthreads();
    red[t] = (t < 128) ? w3[t] * o2[t] : 0.f;
    __syncthreads();
    for (int off = 128; off > 0; off >>= 1) {
        if (t < off) red[t] += red[t + off];
        __syncthreads();
    }
    if (t == 0) out[g] = 1.f / (1.f + __expf(-(red[0] + b3[0])));
}

// ---------------- launch ------------------------------------------------------
extern "C" void kernel_launch(void* const* d_in, const int* in_sizes, int n_in,
                              void* d_out, int out_size)
{
    const int*   x_idx = (const int*)d_in[0];
    const int*   eidx  = (const int*)d_in[1];
    const float* eattr = (const float*)d_in[2];
    const int*   batch = (const int*)d_in[3];
    const float* emb   = (const float*)d_in[4];
    const float* c1[10]; for (int i = 0; i < 10; i++) c1[i] = (const float*)d_in[5 + i];
    const float* c2[10]; for (int i = 0; i < 10; i++) c2[i] = (const float*)d_in[15 + i];
    const float* w1 = (const float*)d_in[25]; const float* b1 = (const float*)d_in[26];
    const float* w2 = (const float*)d_in[27]; const float* b2 = (const float*)d_in[28];
    const float* w3 = (const float*)d_in[29]; const float* b3 = (const float*)d_in[30];

    int N = in_sizes[0] / 8;    // 50000
    int E = in_sizes[1] / 2;    // 300000
    const int* esrc = eidx;
    const int* edst = eidx + E;
    float* out = (float*)d_out;

    // c-layer order: 0 wq, 1 bq, 2 wk, 3 bk, 4 wv, 5 bv, 6 we, 7 be, 8 ws, 9 bs
    long emb_total = (long)N * 512;
    embed_kernel<<<(int)((emb_total + 255) / 256), 256>>>(x_idx, emb, N);
    init_kernel<<<128, 256>>>(N);
    count_kernel<<<(E + 255) / 256, 256>>>(edst, E);
    scan_kernel<<<1, 1024>>>(N);
    fill_kernel<<<(E + 255) / 256, 256>>>(edst, E);

    dim3 ggrid(8, (N + 127) / 128);
    // layer 1: K = 512
    gemm_kernel<<<ggrid, 256>>>(0, N, 512,
        c1[0], c1[2], c1[4], c1[8], c1[1], c1[3], c1[5], c1[9]);
    attn_kernel<<<(N + 7) / 8, 256>>>(0, esrc, eattr, c1[6], c1[7], N);
    // layer 2: K = 256
    gemm_kernel<<<ggrid, 256>>>(1, N, 256,
        c2[0], c2[2], c2[4], c2[8], c2[1], c2[3], c2[5], c2[9]);
    attn_kernel<<<(N + 7) / 8, 256>>>(1, esrc, eattr, c2[6], c2[7], N);

    pool_kernel<<<(N + POOL_CHUNK - 1) / POOL_CHUNK, 256>>>(batch, N);
    mlp_kernel<<<GNUM, 256>>>(w1, b1, w2, b2, w3, b3, out);
}

// round 3
// speedup vs baseline: 1.7977x; 1.7977x over previous
#include <cuda_runtime.h>
#include <cuda_bf16.h>
#include <math_constants.h>
#include <cstdint>

// Problem constants
#define NMAX 50000
#define EMAX 300000
#define GNUM 64

// ===================== PTX helpers (base-target only: sm_80+ features) ======
__device__ __forceinline__ uint32_t smem_u32(const void* p) {
    uint32_t a;
    asm("{ .reg .u64 t; cvta.to.shared.u64 t, %1; cvt.u32.u64 %0, t; }" : "=r"(a) : "l"(p));
    return a;
}
__device__ __forceinline__ void cp16(uint32_t dst, const void* src, bool valid) {
    asm volatile("cp.async.cg.shared.global [%0], [%1], 16, %2;"
                 :: "r"(dst), "l"(src), "r"(valid ? 16 : 0));
}
#define CP_COMMIT() asm volatile("cp.async.commit_group;" ::: "memory")
#define CP_WAIT(n)  asm volatile("cp.async.wait_group %0;" :: "n"(n) : "memory")

__device__ __forceinline__ void ldsm4(uint32_t r[4], uint32_t addr) {
    asm volatile("ldmatrix.sync.aligned.m8n8.x4.shared.b16 {%0,%1,%2,%3}, [%4];"
                 : "=r"(r[0]), "=r"(r[1]), "=r"(r[2]), "=r"(r[3]) : "r"(addr));
}
__device__ __forceinline__ void mma_bf16(float c[4], const uint32_t a[4],
                                         uint32_t b0, uint32_t b1) {
    asm volatile(
        "mma.sync.aligned.m16n8k16.row.col.f32.bf16.bf16.f32 "
        "{%0,%1,%2,%3}, {%4,%5,%6,%7}, {%8,%9}, {%0,%1,%2,%3};"
        : "+f"(c[0]), "+f"(c[1]), "+f"(c[2]), "+f"(c[3])
        : "r"(a[0]), "r"(a[1]), "r"(a[2]), "r"(a[3]), "r"(b0), "r"(b1));
}

// ===================== scratch (device globals) ==============================
__device__ __nv_bfloat16 g_xhi[(size_t)NMAX * 512];
__device__ __nv_bfloat16 g_xlo[(size_t)NMAX * 512];
__device__ __nv_bfloat16 g_hhi[(size_t)NMAX * 256];
__device__ __nv_bfloat16 g_hlo[(size_t)NMAX * 256];
__device__ __nv_bfloat16 g_whi[1024 * 512];
__device__ __nv_bfloat16 g_wlo[1024 * 512];
__device__ float g_bias[1024];
__device__ float g_qkvs[(size_t)NMAX * 1024];   // [q|k|v|skip] per node
__device__ float g_h1[(size_t)NMAX * 256];
__device__ int   g_deg[NMAX];
__device__ int   g_rowptr[NMAX + 1];
__device__ int   g_cursor[NMAX];
__device__ int   g_eids[EMAX];
__device__ int   g_bsum[64];
__device__ int   g_boff[64];
__device__ float g_gap[GNUM * 256];
__device__ unsigned g_gmp[GNUM * 256];
__device__ int   g_cnt[GNUM];

__device__ __forceinline__ void split_bf16(float v, __nv_bfloat16& hi, __nv_bfloat16& lo) {
    hi = __float2bfloat16(v);
    lo = __float2bfloat16(v - __bfloat162float(hi));
}

// ---------------- 1. embedding gather + bf16 split ---------------------------
__global__ void embed_kernel(const int* __restrict__ xidx,
                             const float* __restrict__ emb, int N)
{
    long i = (long)blockIdx.x * blockDim.x + threadIdx.x;
    if (i >= (long)N * 512) return;
    int n = (int)(i >> 9), k = (int)(i & 511);
    int f = k >> 6, j = k & 63;
    float v = emb[(size_t)xidx[n * 8 + f] * 64 + j];
    __nv_bfloat16 hi, lo; split_bf16(v, hi, lo);
    g_xhi[i] = hi; g_xlo[i] = lo;
}

// ---------------- 2. weight split: rows [wq|wk|wv|ws] -> g_whi/g_wlo ---------
__global__ void splitw_kernel(const float* __restrict__ wq, const float* __restrict__ wk,
                              const float* __restrict__ wv, const float* __restrict__ ws,
                              const float* __restrict__ bq, const float* __restrict__ bk,
                              const float* __restrict__ bv, const float* __restrict__ bs,
                              int K)
{
    long idx = (long)blockIdx.x * blockDim.x + threadIdx.x;
    if (idx < 1024) {
        int r = (int)idx;
        const float* bb = (r < 256) ? bq : (r < 512) ? bk : (r < 768) ? bv : bs;
        g_bias[r] = bb[r & 255];
    }
    if (idx >= (long)1024 * K) return;
    int row = (int)(idx / K), col = (int)(idx % K);
    const float* W = (row < 256) ? wq : (row < 512) ? wk : (row < 768) ? wv : ws;
    float v = W[(row & 255) * K + col];
    __nv_bfloat16 hi, lo; split_bf16(v, hi, lo);
    g_whi[idx] = hi; g_wlo[idx] = lo;
}

// ---------------- 3. init + CSR ----------------------------------------------
__global__ void init_kernel(int N)
{
    int i = blockIdx.x * blockDim.x + threadIdx.x;
    int stride = gridDim.x * blockDim.x;
    for (int j = i; j < N; j += stride) g_deg[j] = 0;
    for (int j = i; j < GNUM * 256; j += stride) { g_gap[j] = 0.f; g_gmp[j] = 0u; }
    for (int j = i; j < GNUM; j += stride) g_cnt[j] = 0;
}
__global__ void count_kernel(const int* __restrict__ dst, int E)
{
    int e = blockIdx.x * blockDim.x + threadIdx.x;
    if (e < E) atomicAdd(&g_deg[dst[e]], 1);
}
__global__ void scan1_kernel(int N)
{
    __shared__ int sm[1024];
    int tid = threadIdx.x;
    int i = blockIdx.x * 1024 + tid;
    int v = (i < N) ? g_deg[i] : 0;
    sm[tid] = v;
    __syncthreads();
    #pragma unroll
    for (int off = 1; off < 1024; off <<= 1) {
        int t = (tid >= off) ? sm[tid - off] : 0;
        __syncthreads();
        sm[tid] += t;
        __syncthreads();
    }
    if (i < N) g_rowptr[i + 1] = sm[tid];
    if (tid == 1023) g_bsum[blockIdx.x] = sm[1023];
}
__global__ void scan2_kernel(int nb)
{
    __shared__ int sm[64];
    int tid = threadIdx.x;
    int v = (tid < nb) ? g_bsum[tid] : 0;
    sm[tid] = v;
    __syncthreads();
    #pragma unroll
    for (int off = 1; off < 64; off <<= 1) {
        int t = (tid >= off) ? sm[tid - off] : 0;
        __syncthreads();
        sm[tid] += t;
        __syncthreads();
    }
    g_boff[tid] = sm[tid] - v;
}
__global__ void scan3_kernel(int N)
{
    int i = blockIdx.x * blockDim.x + threadIdx.x;
    if (i < N) {
        int val = g_rowptr[i + 1] + g_boff[i >> 10];
        g_rowptr[i + 1] = val;
        g_cursor[i] = val - g_deg[i];
        if (i == 0) g_rowptr[0] = 0;
    }
}
__global__ void fill_kernel(const int* __restrict__ dst, int E)
{
    int e = blockIdx.x * blockDim.x + threadIdx.x;
    if (e < E) {
        int pos = atomicAdd(&g_cursor[dst[e]], 1);
        g_eids[pos] = e;
    }
}

// ---------------- 4. mma.sync GEMM: C[N,1024] = A @ Wfused^T + bias ----------
// 3-term bf16 split (hi*hi + hi*lo + lo*hi), fp32 accumulation in registers.
// CTA tile 128x128, 8 warps as 2(M)x4(N), warp tile 64x32, BK=32 double-buffered.
#define BM 128
#define BN 128
#define BK 32
#define LDT 80                  // bytes per smem row (32 bf16 + 8 pad)
#define TILE_SZ (BM * LDT)      // 10240 B
#define STAGE_SZ (4 * TILE_SZ)  // Ahi|Alo|Bhi|Blo = 40960 B
#define GEMM_SMEM (2 * STAGE_SZ)

__global__ void __launch_bounds__(256) gemm_tc(int layer, int M, int K)
{
    extern __shared__ char smem[];
    uint32_t sb = smem_u32(smem);
    const __nv_bfloat16* Ahi = layer ? g_hhi : g_xhi;
    const __nv_bfloat16* Alo = layer ? g_hlo : g_xlo;

    int tid = threadIdx.x;
    int m0 = blockIdx.y * BM;
    int n0 = blockIdx.x * BN;
    int wid = tid >> 5, lane = tid & 31;
    int wm = wid & 1, wn = wid >> 1;

    float C[4][4][4];
    #pragma unroll
    for (int a = 0; a < 4; a++)
        #pragma unroll
        for (int b = 0; b < 4; b++)
            #pragma unroll
            for (int c = 0; c < 4; c++) C[a][b][c] = 0.f;

    int S = K / BK;

    // ---- stage prefetch: 512 16B-chunks per array, 2 per thread per array
    auto prefetch = [&](int s) {
        int k0 = s * BK;
        uint32_t base = sb + (s & 1) * STAGE_SZ;
        #pragma unroll
        for (int i = 0; i < 2; i++) {
            int c = tid + i * 256;           // 0..511
            int row = c >> 2;
            int co = (c & 3);                // 16B chunk within the 64B row
            uint32_t doff = row * LDT + co * 16;
            long ka = (long)k0 + co * 8;
            bool v = (m0 + row) < M;
            const __nv_bfloat16* pa = Ahi + (size_t)(m0 + row) * K + ka;
            const __nv_bfloat16* pl = Alo + (size_t)(m0 + row) * K + ka;
            cp16(base + doff, pa, v);
            cp16(base + TILE_SZ + doff, pl, v);
            size_t gb = (size_t)(n0 + row) * K + ka;
            cp16(base + 2 * TILE_SZ + doff, g_whi + gb, true);
            cp16(base + 3 * TILE_SZ + doff, g_wlo + gb, true);
        }
    };

    prefetch(0); CP_COMMIT();

    for (int s = 0; s < S; s++) {
        if (s + 1 < S) { prefetch(s + 1); CP_COMMIT(); CP_WAIT(1); }
        else           { CP_WAIT(0); }
        __syncthreads();
        uint32_t base = sb + (s & 1) * STAGE_SZ;

        #pragma unroll
        for (int ks = 0; ks < 2; ks++) {
            uint32_t Ah[4][4], Al[4][4];
            int arow = wm * 64 + (lane & 15);
            uint32_t acol = ks * 32 + (lane >> 4) * 16;     // bytes
            #pragma unroll
            for (int mt = 0; mt < 4; mt++) {
                uint32_t ad = base + (arow + mt * 16) * LDT + acol;
                ldsm4(Ah[mt], ad);
                ldsm4(Al[mt], ad + TILE_SZ);
            }
            #pragma unroll
            for (int p = 0; p < 2; p++) {
                int mat = lane >> 3, r = lane & 7;
                int brow = wn * 32 + p * 16 + (mat >> 1) * 8 + r;
                uint32_t bcol = ks * 32 + (mat & 1) * 16;
                uint32_t bd = base + 2 * TILE_SZ + brow * LDT + bcol;
                uint32_t Bh[4], Bl[4];
                ldsm4(Bh, bd);
                ldsm4(Bl, bd + TILE_SZ);
                #pragma unroll
                for (int mt = 0; mt < 4; mt++) {
                    #pragma unroll
                    for (int j = 0; j < 2; j++) {
                        float* cc = C[mt][p * 2 + j];
                        mma_bf16(cc, Ah[mt], Bh[j * 2], Bh[j * 2 + 1]);
                        mma_bf16(cc, Ah[mt], Bl[j * 2], Bl[j * 2 + 1]);
                        mma_bf16(cc, Al[mt], Bh[j * 2], Bh[j * 2 + 1]);
                    }
                }
            }
        }
        __syncthreads();
    }

    // ---- epilogue: bias + store fp32
    #pragma unroll
    for (int mt = 0; mt < 4; mt++) {
        int m = m0 + wm * 64 + mt * 16 + (lane >> 2);
        #pragma unroll
        for (int nt = 0; nt < 4; nt++) {
            int n = n0 + wn * 32 + nt * 8 + (lane & 3) * 2;
            float b0 = g_bias[n], b1 = g_bias[n + 1];
            if (m < M) {
                float2 v = make_float2(C[mt][nt][0] + b0, C[mt][nt][1] + b1);
                *(float2*)(g_qkvs + (size_t)m * 1024 + n) = v;
            }
            if (m + 8 < M) {
                float2 v = make_float2(C[mt][nt][2] + b0, C[mt][nt][3] + b1);
                *(float2*)(g_qkvs + (size_t)(m + 8) * 1024 + n) = v;
            }
        }
    }
}

// ---------------- 5. fused edge attention: 1 warp per dst node --------------
__global__ void __launch_bounds__(256) attn_kernel(
    int layer,
    const int* __restrict__ esrc, const float* __restrict__ eattr,
    const float* __restrict__ we, const float* __restrict__ be, int N)
{
    int warp = (int)((blockIdx.x * 256 + threadIdx.x) >> 5);
    int lane = threadIdx.x & 31;
    if (warp >= N) return;

    int d0 = lane * 8;
    float wE[8][6], bE[8];
    #pragma unroll
    for (int i = 0; i < 8; i++) {
        bE[i] = be[d0 + i];
        #pragma unroll
        for (int j = 0; j < 6; j++) wE[i][j] = we[(d0 + i) * 6 + j];
    }

    const float* base = g_qkvs + (size_t)warp * 1024;
    float q[8];
    {
        float4 t0 = *(const float4*)(base + d0);
        float4 t1 = *(const float4*)(base + d0 + 4);
        q[0] = t0.x; q[1] = t0.y; q[2] = t0.z; q[3] = t0.w;
        q[4] = t1.x; q[5] = t1.y; q[6] = t1.z; q[7] = t1.w;
    }

    float m = -CUDART_INF_F, s = 0.f;
    float acc[8] = {0, 0, 0, 0, 0, 0, 0, 0};
    int beg = g_rowptr[warp], end = g_rowptr[warp + 1];

    for (int p = beg; p < end; p++) {
        int eid = g_eids[p];
        int src = esrc[eid];
        float eav = (lane < 6) ? eattr[(size_t)eid * 6 + lane] : 0.f;

        const float* kb = g_qkvs + (size_t)src * 1024 + 256;
        float4 k0 = *(const float4*)(kb + d0);
        float4 k1 = *(const float4*)(kb + d0 + 4);
        float4 v0 = *(const float4*)(kb + 256 + d0);
        float4 v1 = *(const float4*)(kb + 256 + d0 + 4);

        float e6[6];
        #pragma unroll
        for (int j = 0; j < 6; j++) e6[j] = __shfl_sync(0xffffffffu, eav, j);
        float e8[8];
        #pragma unroll
        for (int i = 0; i < 8; i++) {
            float t = bE[i];
            #pragma unroll
            for (int j = 0; j < 6; j++) t += wE[i][j] * e6[j];
            e8[i] = t;
        }
        float kk[8] = {k0.x + e8[0], k0.y + e8[1], k0.z + e8[2], k0.w + e8[3],
                       k1.x + e8[4], k1.y + e8[5], k1.z + e8[6], k1.w + e8[7]};
        float vv[8] = {v0.x + e8[0], v0.y + e8[1], v0.z + e8[2], v0.w + e8[3],
                       v1.x + e8[4], v1.y + e8[5], v1.z + e8[6], v1.w + e8[7]};
        float t = 0.f;
        #pragma unroll
        for (int i = 0; i < 8; i++) t += q[i] * kk[i];
        #pragma unroll
        for (int off = 16; off; off >>= 1) t += __shfl_xor_sync(0xffffffffu, t, off);
        float logit = t * 0.0625f;

        float nm = fmaxf(m, logit);
        float sc = __expf(m - nm);
        float pw = __expf(logit - nm);
        s = s * sc + pw;
        #pragma unroll
        for (int i = 0; i < 8; i++) acc[i] = acc[i] * sc + pw * vv[i];
        m = nm;
    }

    float inv = (s > 0.f) ? (1.f / s) : 0.f;
    const float* sk = base + 768;
    float4 s0 = *(const float4*)(sk + d0);
    float4 s1 = *(const float4*)(sk + d0 + 4);
    float o[8] = {fmaxf(acc[0] * inv + s0.x, 0.f), fmaxf(acc[1] * inv + s0.y, 0.f),
                  fmaxf(acc[2] * inv + s0.z, 0.f), fmaxf(acc[3] * inv + s0.w, 0.f),
                  fmaxf(acc[4] * inv + s1.x, 0.f), fmaxf(acc[5] * inv + s1.y, 0.f),
                  fmaxf(acc[6] * inv + s1.z, 0.f), fmaxf(acc[7] * inv + s1.w, 0.f)};

    if (layer == 0) {
        uint4 uh, ul;
        __nv_bfloat16* ph = (__nv_bfloat16*)&uh;
        __nv_bfloat16* pl = (__nv_bfloat16*)&ul;
        #pragma unroll
        for (int i = 0; i < 8; i++) {
            __nv_bfloat16 hi, lo; split_bf16(o[i], hi, lo);
            ph[i] = hi; pl[i] = lo;
        }
        *(uint4*)(g_hhi + (size_t)warp * 256 + d0) = uh;
        *(uint4*)(g_hlo + (size_t)warp * 256 + d0) = ul;
    } else {
        float* hp = g_h1 + (size_t)warp * 256 + d0;
        *(float4*)hp       = *(const float4*)&o[0];
        *(float4*)(hp + 4) = *(const float4*)&o[4];
    }
}

// ---------------- 6. pooling (sorted batch, run-accumulated atomics) --------
#define POOL_CHUNK 512
__global__ void __launch_bounds__(256) pool_kernel(const int* __restrict__ batch, int N)
{
    int d  = threadIdx.x;
    int n0 = blockIdx.x * POOL_CHUNK;
    if (n0 >= N) return;
    int n1 = min(n0 + POOL_CHUNK, N);

    int cur = batch[n0];
    float sum = 0.f, mx = 0.f;
    int run = 0;
    for (int n = n0; n < n1; n++) {
        int g = batch[n];
        if (g != cur) {
            atomicAdd(&g_gap[cur * 256 + d], sum);
            atomicMax(&g_gmp[cur * 256 + d], __float_as_uint(mx));
            if (d == 0) atomicAdd(&g_cnt[cur], run);
            sum = 0.f; mx = 0.f; run = 0; cur = g;
        }
        float v = g_h1[(size_t)n * 256 + d];
        sum += v; mx = fmaxf(mx, v); run++;
    }
    atomicAdd(&g_gap[cur * 256 + d], sum);
    atomicMax(&g_gmp[cur * 256 + d], __float_as_uint(mx));
    if (d == 0) atomicAdd(&g_cnt[cur], run);
}

// ---------------- 7. head MLP ------------------------------------------------
__global__ void __launch_bounds__(256) mlp_kernel(
    const float* __restrict__ w1, const float* __restrict__ b1,
    const float* __restrict__ w2, const float* __restrict__ b2,
    const float* __restrict__ w3, const float* __restrict__ b3,
    float* __restrict__ out)
{
    int g = blockIdx.x;
    int t = threadIdx.x;
    __shared__ float r[512];
    __shared__ float o1[256];
    __shared__ float o2[128];
    __shared__ float red[256];

    float c = fmaxf((float)g_cnt[g], 1.f);
    r[t]       = g_gap[g * 256 + t] / c;
    r[256 + t] = __uint_as_float(g_gmp[g * 256 + t]);
    __syncthreads();
    {
        float a = b1[t];
        const float* wr = w1 + (size_t)t * 512;
        #pragma unroll 8
        for (int i = 0; i < 512; i++) a += wr[i] * r[i];
        o1[t] = fmaxf(a, 0.f);
    }
    __syncthreads();
    if (t < 128) {
        float a = b2[t];
        const float* wr = w2 + (size_t)t * 256;
        #pragma unroll 8
        for (int i = 0; i < 256; i++) a += wr[i] * o1[i];
        o2[t] = fmaxf(a, 0.f);
    }
    __syncthreads();
    red[t] = (t < 128) ? w3[t] * o2[t] : 0.f;
    __syncthreads();
    for (int off = 128; off > 0; off >>= 1) {
        if (t < off) red[t] += red[t + off];
        __syncthreads();
    }
    if (t == 0) out[g] = 1.f / (1.f + __expf(-(red[0] + b3[0])));
}

// ---------------- launch ------------------------------------------------------
extern "C" void kernel_launch(void* const* d_in, const int* in_sizes, int n_in,
                              void* d_out, int out_size)
{
    const int*   x_idx = (const int*)d_in[0];
    const int*   eidx  = (const int*)d_in[1];
    const float* eattr = (const float*)d_in[2];
    const int*   batch = (const int*)d_in[3];
    const float* emb   = (const float*)d_in[4];
    const float* c1[10]; for (int i = 0; i < 10; i++) c1[i] = (const float*)d_in[5 + i];
    const float* c2[10]; for (int i = 0; i < 10; i++) c2[i] = (const float*)d_in[15 + i];
    const float* w1 = (const float*)d_in[25]; const float* b1 = (const float*)d_in[26];
    const float* w2 = (const float*)d_in[27]; const float* b2 = (const float*)d_in[28];
    const float* w3 = (const float*)d_in[29]; const float* b3 = (const float*)d_in[30];

    int N = in_sizes[0] / 8;    // 50000
    int E = in_sizes[1] / 2;    // 300000
    const int* esrc = eidx;
    const int* edst = eidx + E;
    float* out = (float*)d_out;

    cudaFuncSetAttribute(gemm_tc, cudaFuncAttributeMaxDynamicSharedMemorySize, GEMM_SMEM);

    long emb_total = (long)N * 512;
    embed_kernel<<<(int)((emb_total + 255) / 256), 256>>>(x_idx, emb, N);
    init_kernel<<<128, 256>>>(N);
    count_kernel<<<(E + 255) / 256, 256>>>(edst, E);
    int nb = (N + 1023) / 1024;
    scan1_kernel<<<nb, 1024>>>(N);
    scan2_kernel<<<1, 64>>>(nb);
    scan3_kernel<<<(N + 255) / 256, 256>>>(N);
    fill_kernel<<<(E + 255) / 256, 256>>>(edst, E);

    dim3 ggrid(8, (N + 127) / 128);
    // layer 1 (K = 512): c order: 0 wq,1 bq,2 wk,3 bk,4 wv,5 bv,6 we,7 be,8 ws,9 bs
    splitw_kernel<<<(1024 * 512 + 255) / 256, 256>>>(
        c1[0], c1[2], c1[4], c1[8], c1[1], c1[3], c1[5], c1[9], 512);
    gemm_tc<<<ggrid, 256, GEMM_SMEM>>>(0, N, 512);
    attn_kernel<<<(N + 7) / 8, 256>>>(0, esrc, eattr, c1[6], c1[7], N);
    // layer 2 (K = 256)
    splitw_kernel<<<(1024 * 256 + 255) / 256, 256>>>(
        c2[0], c2[2], c2[4], c2[8], c2[1], c2[3], c2[5], c2[9], 256);
    gemm_tc<<<ggrid, 256, GEMM_SMEM>>>(1, N, 256);
    attn_kernel<<<(N + 7) / 8, 256>>>(1, esrc, eattr, c2[6], c2[7], N);

    pool_kernel<<<(N + POOL_CHUNK - 1) / POOL_CHUNK, 256>>>(batch, N);
    mlp_kernel<<<GNUM, 256>>>(w1, b1, w2, b2, w3, b3, out);
}